// round 14
// baseline (speedup 1.0000x reference)
#include <cuda_runtime.h>
#include <cuda_bf16.h>
#include <cstdint>

#define NN 8192
#define LEAK 0.7f

// ---------------- global scratch ----------------
__device__ __align__(16) __nv_bfloat16 gUh[NN * 64], gUl[NN * 64];
__device__ __align__(16) __nv_bfloat16 gVch[2][(NN + 64) * 64], gVcl[2][(NN + 64) * 64];
__device__ __align__(16) char gE8[2][128 * 8192];  // [b][chunk: hi 4096 | lo 4096], [d][i]
__device__ int g_idx[2][NN + 64];
__device__ int g_cnt[2];

// ---------------- helpers ----------------
__device__ __forceinline__ uint32_t smem_u32(const void* p) {
    uint32_t a;
    asm("{ .reg .u64 t; cvta.to.shared.u64 t, %1; cvt.u32.u64 %0, t; }" : "=r"(a) : "l"(p));
    return a;
}
#define LDSM4(R0, R1, R2, R3, A)                                                 \
    asm volatile("ldmatrix.sync.aligned.m8n8.x4.shared.b16 {%0,%1,%2,%3}, [%4];" \
                 : "=r"(R0), "=r"(R1), "=r"(R2), "=r"(R3) : "r"(A))
#define MMA_BF16(c, a0, a1, a2, a3, b0, b1)                                   \
    asm volatile("mma.sync.aligned.m16n8k16.row.col.f32.bf16.bf16.f32 "       \
                 "{%0,%1,%2,%3},{%4,%5,%6,%7},{%8,%9},{%0,%1,%2,%3};"         \
                 : "+f"((c)[0]), "+f"((c)[1]), "+f"((c)[2]), "+f"((c)[3])     \
                 : "r"(a0), "r"(a1), "r"(a2), "r"(a3), "r"(b0), "r"(b1))
#define MMA_S8(c, a0, a1, a2, a3, b0, b1)                                     \
    asm volatile("mma.sync.aligned.m16n8k32.row.col.s32.s8.s8.s32 "           \
                 "{%0,%1,%2,%3},{%4,%5,%6,%7},{%8,%9},{%0,%1,%2,%3};"         \
                 : "+r"((c)[0]), "+r"((c)[1]), "+r"((c)[2]), "+r"((c)[3])     \
                 : "r"(a0), "r"(a1), "r"(a2), "r"(a3), "r"(b0), "r"(b1))
#define CP16(dst, src) \
    asm volatile("cp.async.cg.shared.global [%0], [%1], 16;" :: "r"(dst), "l"(src))
#define CP_COMMIT() asm volatile("cp.async.commit_group;" ::: "memory")
#define CP_WAIT0()  asm volatile("cp.async.wait_group 0;" ::: "memory")

__device__ __forceinline__ void split2(float x, __nv_bfloat16& h, __nv_bfloat16& l) {
    h = __float2bfloat16(x);
    l = __float2bfloat16(x - __bfloat162float(h));
}
__device__ __forceinline__ uint32_t pack2(__nv_bfloat16 a, __nv_bfloat16 b) {
    return (uint32_t)__bfloat16_as_ushort(a) | ((uint32_t)__bfloat16_as_ushort(b) << 16);
}

// ---------------- kernel 1: per-batch scan, one block per batch ----------------
__global__ void __launch_bounds__(1024) prep_scan(const float* __restrict__ prof) {
    __shared__ int wsum[32];
    __shared__ int s_cnt;
    const int b = blockIdx.x;
    const int tid = threadIdx.x;
    const int base = tid * 8;

    uint32_t m = 0;
    int local = 0;
#pragma unroll
    for (int q = 0; q < 8; q++) {
        int a = prof[b * NN + base + q] > LEAK;
        m |= ((uint32_t)a) << q;
        local += a;
    }
    int lane = tid & 31, wid = tid >> 5;
    int inc = local;
#pragma unroll
    for (int d = 1; d < 32; d <<= 1) {
        int v = __shfl_up_sync(~0u, inc, d);
        if (lane >= d) inc += v;
    }
    if (lane == 31) wsum[wid] = inc;
    __syncthreads();
    if (wid == 0) {
        int v = wsum[lane];
#pragma unroll
        for (int d = 1; d < 32; d <<= 1) {
            int u = __shfl_up_sync(~0u, v, d);
            if (lane >= d) v += u;
        }
        wsum[lane] = v;
        if (lane == 31) s_cnt = v;
    }
    __syncthreads();
    int excl = inc - local + (wid > 0 ? wsum[wid - 1] : 0);
#pragma unroll
    for (int q = 0; q < 8; q++)
        if ((m >> q) & 1) g_idx[b][excl++] = base + q;

    int cnt = s_cnt;
    if (tid == 0) g_cnt[b] = cnt;
    int pad_end = (cnt + 63) & ~63;
    for (int p = cnt + tid; p < pad_end; p += 1024) g_idx[b][p] = -1;
}

// ---------------- kernel 2: U split (blocks 0..127) + per-chunk V,E (128..383) ----
__global__ void __launch_bounds__(256) prep_all(const float* __restrict__ U,
                                                const float* __restrict__ W,
                                                const float* __restrict__ S,
                                                const float* __restrict__ prof) {
    int tid = threadIdx.x;
    if (blockIdx.x < 128) {
        int base4 = blockIdx.x * 1024;
        const float4* U4 = (const float4*)U;
#pragma unroll
        for (int idx = tid; idx < 1024; idx += 256) {
            float4 u = U4[base4 + idx];
            __nv_bfloat16 h0, l0, h1, l1, h2, l2, h3, l3;
            split2(u.x, h0, l0); split2(u.y, h1, l1);
            split2(u.z, h2, l2); split2(u.w, h3, l3);
            uint2 hh, ll;
            hh.x = pack2(h0, h1); hh.y = pack2(h2, h3);
            ll.x = pack2(l0, l1); ll.y = pack2(l2, l3);
            ((uint2*)gUh)[base4 + idx] = hh;
            ((uint2*)gUl)[base4 + idx] = ll;
        }
        return;
    }

    int lin = blockIdx.x - 128;
    int b = lin >> 7, c = lin & 127;
    int nt = (g_cnt[b] + 63) >> 6;
    if (c >= nt) return;

    __shared__ float Wt[64 * 68];    // [col][e]; reused as es[64][65]
    __shared__ float Ur[64 * 64];
    __shared__ float sg[64];
    __shared__ int sidx[64];

    if (tid < 64) {
        int gi = g_idx[b][c * 64 + tid];
        sidx[tid] = gi;
        float g0 = 0.f;
        if (gi >= 0) {
            g0 = prof[b * NN + gi] - LEAK;
            g0 = g0 > 0.f ? g0 : 0.f;
        }
        sg[tid] = g0;
    }
    for (int i = tid; i < 4096; i += 256) {
        int col = i & 63, e = i >> 6;
        Wt[col * 68 + e] = W[e * 64 + col];
    }
    __syncthreads();

    {
        const float4* U4 = (const float4*)U;
        float4* Ur4 = (float4*)Ur;
        for (int idx = tid; idx < 1024; idx += 256) {
            int r = idx >> 4, f4 = idx & 15;
            int gi = sidx[r];
            Ur4[idx] = (gi >= 0) ? U4[gi * 16 + f4] : make_float4(0.f, 0.f, 0.f, 0.f);
        }
    }
    __syncthreads();

    {
        int col = tid & 63, rq = tid >> 6;
        float acc[16];
#pragma unroll
        for (int q = 0; q < 16; q++) acc[q] = 0.f;
        const float4* wt4 = (const float4*)(Wt + col * 68);
        const float4* Ur4 = (const float4*)Ur;
#pragma unroll
        for (int e4 = 0; e4 < 16; e4++) {
            float4 wv = wt4[e4];
#pragma unroll
            for (int q = 0; q < 16; q++) {
                float4 uv = Ur4[(4 * q + rq) * 16 + e4];
                acc[q] += uv.x * wv.x + uv.y * wv.y + uv.z * wv.z + uv.w * wv.w;
            }
        }
#pragma unroll
        for (int q = 0; q < 16; q++) {
            int r = 4 * q + rq;
            __nv_bfloat16 h, lo;
            split2(acc[q], h, lo);
            gVch[b][(c * 64 + r) * 64 + col] = h;
            gVcl[b][(c * 64 + r) * 64 + col] = lo;
        }
    }
    __syncthreads();

    // E: gather gated S into es[i][d], then write int8 digit planes [d][i]
    for (int idx = tid; idx < 4096; idx += 256) {
        int r = idx >> 6, d = idx & 63;
        int gi = sidx[r];
        Wt[r * 65 + d] = (gi >= 0) ? S[((size_t)b * NN + gi) * 64 + d] * sg[r] : 0.f;
    }
    __syncthreads();
    {
        int base = c * 8192;
        for (int idx = tid; idx < 4096; idx += 256) {
            int d = idx >> 6, i = idx & 63;
            float x = Wt[i * 65 + d];
            int X = __float2int_rn(x * 16128.f);
            X = max(-32256, min(32256, X));
            int Xh = (X + 128) >> 8;
            int Xl = X - (Xh << 8);
            gE8[b][base + d * 64 + i] = (char)Xh;
            gE8[b][base + 4096 + d * 64 + i] = (char)Xl;
        }
    }
}

// ---------------- main ----------------
// smem: U (18432) | V stages 2x18688 (Vh 9216, Vl 9216, idx 256) |
//       E stages 3x10240 (hi 64x80, lo 64x80) | P bufs 2x10240 (4 mj x 2 dig x 16x80)
#define SM_U 0u
#define SM_V 18432u
#define VSLOT 18688u
#define SM_E 55808u
#define ESLOT 10240u
#define SM_P 86528u
#define PBUF 10240u
#define SM_TOTAL 107008u

__device__ __forceinline__ void stage_load(uint32_t sb, int b, int t, int tid) {
    uint32_t slotV = sb + SM_V + (uint32_t)(t & 1) * VSLOT;
    uint32_t slotE = sb + SM_E + (uint32_t)(t % 3) * ESLOT;
#pragma unroll
    for (int idx = tid; idx < 1024; idx += 256) {
        int h = idx >> 9, rem = idx & 511, r = rem >> 3, c = rem & 7;
        uint32_t dst = slotV + h * 9216u + r * 144u + c * 16u;
        const char* src = (const char*)(h ? gVcl[b] : gVch[b]) +
                          ((size_t)t * 4096 + r * 64 + c * 8) * 2;
        CP16(dst, src);
    }
#pragma unroll
    for (int idx = tid; idx < 512; idx += 256) {
        int dg = idx >> 8, rem = idx & 255, r = rem >> 2, c = rem & 3;
        uint32_t dst = slotE + dg * 5120u + r * 80u + c * 16u;
        const char* src = gE8[b] + (size_t)t * 8192 + dg * 4096 + r * 64 + c * 16;
        CP16(dst, src);
    }
    if (tid < 16)
        CP16(slotV + 18432u + tid * 16u, (const char*)(g_idx[b] + t * 64) + tid * 16);
}

__global__ void __launch_bounds__(256, 2) dyadic_mma(const float* __restrict__ S,
                                                     const float* __restrict__ bias_p,
                                                     float* __restrict__ out) {
    extern __shared__ char sm[];
    const uint32_t sb = smem_u32(sm);
    const int tid = threadIdx.x, w = tid >> 5, lane = tid & 31;
    const int jc = blockIdx.x >> 1, b = blockIdx.x & 1;
    const float bias = bias_p[0];
    const int nt = (g_cnt[b] + 63) >> 6;

    const int g = lane >> 2, tig = lane & 3;
    const int a_r = lane & 15;
    const int a_c = (lane & 16) ? 8 : 0;   // bf16 half-col (units of b16 for V/U)
    const int i_c = (lane & 16) ? 16 : 0;  // byte half-col for int8 tiles
    const int b_r = (lane & 7) + ((lane & 16) ? 8 : 0);
    const int b_c = (lane & 8) ? 8 : 0;

    const int mj = w & 3;   // j slice [16*mj, +16) -- both GEMMs
    const int nw = w >> 2;  // G1 i slice [32*nw, +32)
    const int nd = w >> 2;  // G2 d slice [32*nd, +32)

    // stage resident U tile
    {
        const uint4* sh = (const uint4*)gUh + jc * 512;
        const uint4* sl = (const uint4*)gUl + jc * 512;
        for (int idx = tid; idx < 512; idx += 256) {
            int r = idx >> 3, c = idx & 7;
            *(uint4*)(sm + SM_U + r * 144 + c * 16) = sh[idx];
            *(uint4*)(sm + SM_U + 9216 + r * 144 + c * 16) = sl[idx];
        }
    }

    int d2hh[4][4], d2cr[4][4];
#pragma unroll
    for (int nb = 0; nb < 4; nb++)
#pragma unroll
        for (int q = 0; q < 4; q++) { d2hh[nb][q] = 0; d2cr[nb][q] = 0; }

    const uint32_t ua = sb + SM_U + (16 * mj + a_r) * 144 + a_c * 2;
    const uint32_t pA0 = sb + SM_P + mj * 2560u + (uint32_t)(lane & 15) * 80u + i_c;
    const uint32_t eB0 = sb + SM_E + (uint32_t)(32 * nd + (lane & 15)) * 80u + i_c;

    if (nt > 0) {
        stage_load(sb, b, 0, tid);
        CP_COMMIT();

        for (int t = 0; t < nt; t++) {
            CP_WAIT0();
            __syncthreads();  // stage t + P(t-1) visible everywhere

            if (t + 1 < nt) {
                stage_load(sb, b, t + 1, tid);
                CP_COMMIT();
            }

            // ---- GEMM2(t-1): int8 two-digit, D2[16j x 32d] ----
            if (t > 0) {
                const int tc = t - 1;
                const uint32_t pA = pA0 + (uint32_t)(tc & 1) * PBUF;
                const uint32_t eB = eB0 + (uint32_t)(tc % 3) * ESLOT;
#pragma unroll
                for (int ks2 = 0; ks2 < 2; ks2++) {
                    uint32_t ah[4], al[4];
                    LDSM4(ah[0], ah[1], ah[2], ah[3], pA + ks2 * 32);
                    LDSM4(al[0], al[1], al[2], al[3], pA + 1280u + ks2 * 32);
                    uint32_t eh[2][4], el[2][4];
#pragma unroll
                    for (int nbp = 0; nbp < 2; nbp++) {
                        LDSM4(eh[nbp][0], eh[nbp][1], eh[nbp][2], eh[nbp][3],
                              eB + nbp * 1280u + ks2 * 32);
                        LDSM4(el[nbp][0], el[nbp][1], el[nbp][2], el[nbp][3],
                              eB + 5120u + nbp * 1280u + ks2 * 32);
                    }
#pragma unroll
                    for (int nb = 0; nb < 4; nb++) {
                        int nbp = nb >> 1, od = nb & 1;
                        MMA_S8(d2hh[nb], ah[0], ah[1], ah[2], ah[3],
                               eh[nbp][od], eh[nbp][2 + od]);
                        MMA_S8(d2cr[nb], ah[0], ah[1], ah[2], ah[3],
                               el[nbp][od], el[nbp][2 + od]);
                        MMA_S8(d2cr[nb], al[0], al[1], al[2], al[3],
                               eh[nbp][od], eh[nbp][2 + od]);
                    }
                }
            }

            // ---- GEMM1(t): bf16 3-pass, C[16j x 32i] ----
            const uint32_t slotV = sb + SM_V + (uint32_t)(t & 1) * VSLOT;
            uint32_t uah[4][4], ual[4][4];
#pragma unroll
            for (int ks = 0; ks < 4; ks++) {
                LDSM4(uah[ks][0], uah[ks][1], uah[ks][2], uah[ks][3], ua + ks * 32);
                LDSM4(ual[ks][0], ual[ks][1], ual[ks][2], ual[ks][3], ua + 9216u + ks * 32);
            }
            float c1[4][4];
#pragma unroll
            for (int nb = 0; nb < 4; nb++)
#pragma unroll
                for (int q = 0; q < 4; q++) c1[nb][q] = 0.f;

            const uint32_t vbh = slotV + (32 * nw + b_r) * 144 + b_c * 2;
#pragma unroll
            for (int ks = 0; ks < 4; ks++) {
                uint32_t bh[8], bl[8];
#pragma unroll
                for (int p = 0; p < 2; p++) {
                    LDSM4(bh[4 * p], bh[4 * p + 1], bh[4 * p + 2], bh[4 * p + 3],
                          vbh + p * 16 * 144 + ks * 32);
                    LDSM4(bl[4 * p], bl[4 * p + 1], bl[4 * p + 2], bl[4 * p + 3],
                          vbh + 9216u + p * 16 * 144 + ks * 32);
                }
#pragma unroll
                for (int nb = 0; nb < 4; nb++) {
                    int bi = (nb >> 1) * 4 + (nb & 1) * 2;
                    MMA_BF16(c1[nb], uah[ks][0], uah[ks][1], uah[ks][2], uah[ks][3],
                             bh[bi], bh[bi + 1]);
                    MMA_BF16(c1[nb], uah[ks][0], uah[ks][1], uah[ks][2], uah[ks][3],
                             bl[bi], bl[bi + 1]);
                    MMA_BF16(c1[nb], ual[ks][0], ual[ks][1], ual[ks][2], ual[ks][3],
                             bh[bi], bh[bi + 1]);
                }
            }

            // ---- epilogue: sigmoid + mask -> int8 digits -> P smem (t&1) ----
            {
                char* pb = sm + SM_P + (t & 1) * PBUF + mj * 2560 + 32 * nw + 2 * tig;
#pragma unroll
                for (int nb = 0; nb < 4; nb++) {
                    uint32_t i0, i1;
                    asm volatile("ld.shared.v2.u32 {%0,%1}, [%2];" : "=r"(i0), "=r"(i1)
                                 : "r"(slotV + 18432u + (uint32_t)(32 * nw + 8 * nb + 2 * tig) * 4u));
                    int Xq[4];
#pragma unroll
                    for (int q = 0; q < 4; q++) {
                        float x = c1[nb][q] + bias;
                        float s = __fdividef(1.f, 1.f + __expf(-x));
                        int gi = (int)((q & 1) ? i1 : i0);
                        int jg = 64 * jc + 16 * mj + g + ((q & 2) ? 8 : 0);
                        if (gi == jg) s = 0.f;
                        Xq[q] = __float2int_rn(s * 32256.f);
                    }
#pragma unroll
                    for (int half = 0; half < 2; half++) {
                        int X0 = Xq[2 * half + 0], X1 = Xq[2 * half + 1];
                        int h0 = (X0 + 128) >> 8, h1 = (X1 + 128) >> 8;
                        int l0 = X0 - (h0 << 8), l1 = X1 - (h1 << 8);
                        int row = g + 8 * half;
                        *(uint16_t*)(pb + row * 80 + 8 * nb) =
                            (uint16_t)((h0 & 255) | ((h1 & 255) << 8));
                        *(uint16_t*)(pb + 1280 + row * 80 + 8 * nb) =
                            (uint16_t)((l0 & 255) | ((l1 & 255) << 8));
                    }
                }
            }
        }

        __syncthreads();  // P(nt-1) visible
        // ---- final GEMM2(nt-1) ----
        {
            const int tc = nt - 1;
            const uint32_t pA = pA0 + (uint32_t)(tc & 1) * PBUF;
            const uint32_t eB = eB0 + (uint32_t)(tc % 3) * ESLOT;
#pragma unroll
            for (int ks2 = 0; ks2 < 2; ks2++) {
                uint32_t ah[4], al[4];
                LDSM4(ah[0], ah[1], ah[2], ah[3], pA + ks2 * 32);
                LDSM4(al[0], al[1], al[2], al[3], pA + 1280u + ks2 * 32);
                uint32_t eh[2][4], el[2][4];
#pragma unroll
                for (int nbp = 0; nbp < 2; nbp++) {
                    LDSM4(eh[nbp][0], eh[nbp][1], eh[nbp][2], eh[nbp][3],
                          eB + nbp * 1280u + ks2 * 32);
                    LDSM4(el[nbp][0], el[nbp][1], el[nbp][2], el[nbp][3],
                          eB + 5120u + nbp * 1280u + ks2 * 32);
                }
#pragma unroll
                for (int nb = 0; nb < 4; nb++) {
                    int nbp = nb >> 1, od = nb & 1;
                    MMA_S8(d2hh[nb], ah[0], ah[1], ah[2], ah[3],
                           eh[nbp][od], eh[nbp][2 + od]);
                    MMA_S8(d2cr[nb], ah[0], ah[1], ah[2], ah[3],
                           el[nbp][od], el[nbp][2 + od]);
                    MMA_S8(d2cr[nb], al[0], al[1], al[2], al[3],
                           eh[nbp][od], eh[nbp][2 + od]);
                }
            }
        }
    }

    // ---- store: out = S + s_P*s_E*(65536*hh + 256*cr), warp owns 16j x 32d ----
    {
        const float k1 = 65536.f / (32256.f * 16128.f);
        const float k2 = 256.f / (32256.f * 16128.f);
#pragma unroll
        for (int nb = 0; nb < 4; nb++) {
            int d = 32 * nd + 8 * nb + 2 * tig;
#pragma unroll
            for (int half = 0; half < 2; half++) {
                int j = 64 * jc + 16 * mj + g + 8 * half;
                size_t off = ((size_t)(b * NN + j)) * 64 + d;
                float2 sv = *(const float2*)(S + off);
                float2 ov;
                ov.x = sv.x + fmaf((float)d2hh[nb][2 * half + 0], k1,
                                   (float)d2cr[nb][2 * half + 0] * k2);
                ov.y = sv.y + fmaf((float)d2hh[nb][2 * half + 1], k1,
                                   (float)d2cr[nb][2 * half + 1] * k2);
                *(float2*)(out + off) = ov;
            }
        }
    }
}

extern "C" void kernel_launch(void* const* d_in, const int* in_sizes, int n_in,
                              void* d_out, int out_size) {
    const float* S    = (const float*)d_in[0];  // task_states   [2,8192,64]
    const float* prof = (const float*)d_in[1];  // proficiency   [2,8192]
    const float* U    = (const float*)d_in[2];  // task_embeddings [8192,64]
    const float* W    = (const float*)d_in[3];  // bilinear_weight [1,64,64]
    const float* bias = (const float*)d_in[4];  // bilinear_bias  [1]
    float* out = (float*)d_out;

    prep_scan<<<2, 1024>>>(prof);
    prep_all<<<384, 256>>>(U, W, S, prof);

    cudaFuncSetAttribute(dyadic_mma, cudaFuncAttributeMaxDynamicSharedMemorySize, SM_TOTAL);
    dyadic_mma<<<256, 256, SM_TOTAL>>>(S, bias, out);
}

// round 15
// speedup vs baseline: 2.4137x; 2.4137x over previous
#include <cuda_runtime.h>
#include <cuda_fp16.h>
#include <cstdint>

#define NN 8192
#define LEAK 0.7f

// ---------------- global scratch (fp16) ----------------
__device__ __align__(16) __half gUh[NN * 64];                    // U[row][k]
__device__ __align__(16) __half gVch[2][(NN + 64) * 64];         // compacted V
__device__ __align__(16) __half gEh[2][128 * 4096], gEl[2][128 * 4096]; // [b][c][d][i] hi/lo
__device__ int g_idx[2][NN + 64];
__device__ int g_cnt[2];

// ---------------- helpers ----------------
__device__ __forceinline__ uint32_t smem_u32(const void* p) {
    uint32_t a;
    asm("{ .reg .u64 t; cvta.to.shared.u64 t, %1; cvt.u32.u64 %0, t; }" : "=r"(a) : "l"(p));
    return a;
}
#define LDSM4(R0, R1, R2, R3, A)                                                 \
    asm volatile("ldmatrix.sync.aligned.m8n8.x4.shared.b16 {%0,%1,%2,%3}, [%4];" \
                 : "=r"(R0), "=r"(R1), "=r"(R2), "=r"(R3) : "r"(A))
#define MMA_F16(c, a0, a1, a2, a3, b0, b1)                                    \
    asm volatile("mma.sync.aligned.m16n8k16.row.col.f32.f16.f16.f32 "         \
                 "{%0,%1,%2,%3},{%4,%5,%6,%7},{%8,%9},{%0,%1,%2,%3};"         \
                 : "+f"((c)[0]), "+f"((c)[1]), "+f"((c)[2]), "+f"((c)[3])     \
                 : "r"(a0), "r"(a1), "r"(a2), "r"(a3), "r"(b0), "r"(b1))
#define CP16(dst, src) \
    asm volatile("cp.async.cg.shared.global [%0], [%1], 16;" :: "r"(dst), "l"(src))
#define CP_COMMIT() asm volatile("cp.async.commit_group;" ::: "memory")
#define CP_WAIT0()  asm volatile("cp.async.wait_group 0;" ::: "memory")

__device__ __forceinline__ void split2h(float x, __half& h, __half& l) {
    h = __float2half_rn(x);
    l = __float2half_rn(x - __half2float(h));
}
__device__ __forceinline__ uint32_t pack2h(__half a, __half b) {
    return (uint32_t)__half_as_ushort(a) | ((uint32_t)__half_as_ushort(b) << 16);
}

// ---------------- kernel 1: per-batch scan, one block per batch ----------------
__global__ void __launch_bounds__(1024) prep_scan(const float* __restrict__ prof) {
    __shared__ int wsum[32];
    __shared__ int s_cnt;
    const int b = blockIdx.x;
    const int tid = threadIdx.x;
    const int base = tid * 8;

    uint32_t m = 0;
    int local = 0;
#pragma unroll
    for (int q = 0; q < 8; q++) {
        int a = prof[b * NN + base + q] > LEAK;
        m |= ((uint32_t)a) << q;
        local += a;
    }
    int lane = tid & 31, wid = tid >> 5;
    int inc = local;
#pragma unroll
    for (int d = 1; d < 32; d <<= 1) {
        int v = __shfl_up_sync(~0u, inc, d);
        if (lane >= d) inc += v;
    }
    if (lane == 31) wsum[wid] = inc;
    __syncthreads();
    if (wid == 0) {
        int v = wsum[lane];
#pragma unroll
        for (int d = 1; d < 32; d <<= 1) {
            int u = __shfl_up_sync(~0u, v, d);
            if (lane >= d) v += u;
        }
        wsum[lane] = v;
        if (lane == 31) s_cnt = v;
    }
    __syncthreads();
    int excl = inc - local + (wid > 0 ? wsum[wid - 1] : 0);
#pragma unroll
    for (int q = 0; q < 8; q++)
        if ((m >> q) & 1) g_idx[b][excl++] = base + q;

    int cnt = s_cnt;
    if (tid == 0) g_cnt[b] = cnt;
    int pad_end = (cnt + 63) & ~63;
    for (int p = cnt + tid; p < pad_end; p += 1024) g_idx[b][p] = -1;
}

// ---------------- kernel 2: U convert (blocks 0..127) + per-chunk V,E (128..383) ----
__global__ void __launch_bounds__(256) prep_all(const float* __restrict__ U,
                                                const float* __restrict__ W,
                                                const float* __restrict__ S,
                                                const float* __restrict__ prof) {
    int tid = threadIdx.x;
    if (blockIdx.x < 128) {
        int base4 = blockIdx.x * 1024;
        const float4* U4 = (const float4*)U;
#pragma unroll
        for (int idx = tid; idx < 1024; idx += 256) {
            float4 u = U4[base4 + idx];
            uint2 hh;
            hh.x = pack2h(__float2half_rn(u.x), __float2half_rn(u.y));
            hh.y = pack2h(__float2half_rn(u.z), __float2half_rn(u.w));
            ((uint2*)gUh)[base4 + idx] = hh;
        }
        return;
    }

    int lin = blockIdx.x - 128;
    int b = lin >> 7, c = lin & 127;
    int nt = (g_cnt[b] + 63) >> 6;
    if (c >= nt) return;

    __shared__ float Wt[64 * 68];    // [col][e]; reused as es[64][65]
    __shared__ float Ur[64 * 64];
    __shared__ float sg[64];
    __shared__ int sidx[64];

    if (tid < 64) {
        int gi = g_idx[b][c * 64 + tid];
        sidx[tid] = gi;
        float g0 = 0.f;
        if (gi >= 0) {
            g0 = prof[b * NN + gi] - LEAK;
            g0 = g0 > 0.f ? g0 : 0.f;
        }
        sg[tid] = g0;
    }
    for (int i = tid; i < 4096; i += 256) {
        int col = i & 63, e = i >> 6;
        Wt[col * 68 + e] = W[e * 64 + col];
    }
    __syncthreads();

    {
        const float4* U4 = (const float4*)U;
        float4* Ur4 = (float4*)Ur;
        for (int idx = tid; idx < 1024; idx += 256) {
            int r = idx >> 4, f4 = idx & 15;
            int gi = sidx[r];
            Ur4[idx] = (gi >= 0) ? U4[gi * 16 + f4] : make_float4(0.f, 0.f, 0.f, 0.f);
        }
    }
    __syncthreads();

    {
        int col = tid & 63, rq = tid >> 6;
        float acc[16];
#pragma unroll
        for (int q = 0; q < 16; q++) acc[q] = 0.f;
        const float4* wt4 = (const float4*)(Wt + col * 68);
        const float4* Ur4 = (const float4*)Ur;
#pragma unroll
        for (int e4 = 0; e4 < 16; e4++) {
            float4 wv = wt4[e4];
#pragma unroll
            for (int q = 0; q < 16; q++) {
                float4 uv = Ur4[(4 * q + rq) * 16 + e4];
                acc[q] += uv.x * wv.x + uv.y * wv.y + uv.z * wv.z + uv.w * wv.w;
            }
        }
#pragma unroll
        for (int q = 0; q < 16; q++) {
            int r = 4 * q + rq;
            gVch[b][(c * 64 + r) * 64 + col] = __float2half_rn(acc[q]);
        }
    }
    __syncthreads();

    // E: gather gated S into es[i][d], then write fp16 hi/lo planes [d][i]
    for (int idx = tid; idx < 4096; idx += 256) {
        int r = idx >> 6, d = idx & 63;
        int gi = sidx[r];
        Wt[r * 65 + d] = (gi >= 0) ? S[((size_t)b * NN + gi) * 64 + d] * sg[r] : 0.f;
    }
    __syncthreads();
    {
        int base = c * 4096;
        for (int idx = tid; idx < 4096; idx += 256) {
            int d = idx >> 6, i = idx & 63;
            float x = Wt[i * 65 + d];
            __half h, l;
            split2h(x, h, l);
            gEh[b][base + d * 64 + i] = h;
            gEl[b][base + d * 64 + i] = l;
        }
    }
}

// ---------------- main: per-(j-tile, batch) CTA, 2 CTAs/SM ----------------
// stage: V[0,9216) Eh[9216,18432) El[18432,27648) idx[27648,27904)
#define SM_U 0u
#define SM_STG 9216u
#define STG_SZ 27904u
#define OFF_EH 9216u
#define OFF_EL 18432u
#define OFF_IDX 27648u
#define SM_TOTAL (9216u + 2u * 27904u)   // 65024

__device__ __forceinline__ void stage_load(uint32_t stg, int b, int t, int tid) {
#pragma unroll
    for (int idx = tid; idx < 512; idx += 256) {
        int r = idx >> 3, c = idx & 7;
        uint32_t dst = stg + r * 144u + c * 16u;
        const char* src = (const char*)gVch[b] + ((size_t)t * 4096 + r * 64 + c * 8) * 2;
        CP16(dst, src);
    }
#pragma unroll
    for (int idx = tid; idx < 1024; idx += 256) {
        int pl = idx >> 9, rem = idx & 511, r = rem >> 3, c = rem & 7;
        uint32_t dst = stg + OFF_EH + pl * 9216u + r * 144u + c * 16u;
        const char* src = (const char*)(pl ? gEl[b] : gEh[b]) +
                          ((size_t)t * 4096 + r * 64 + c * 8) * 2;
        CP16(dst, src);
    }
    if (tid < 16)
        CP16(stg + OFF_IDX + tid * 16u, (const char*)(g_idx[b] + t * 64) + tid * 16);
}

__global__ void __launch_bounds__(256, 2) dyadic_mma(const float* __restrict__ S,
                                                     const float* __restrict__ bias_p,
                                                     float* __restrict__ out) {
    extern __shared__ char sm[];
    const uint32_t sb = smem_u32(sm);
    const int tid = threadIdx.x, w = tid >> 5, lane = tid & 31;
    const int jc = blockIdx.x >> 1, b = blockIdx.x & 1;
    const float bias = bias_p[0];
    const int nt = (g_cnt[b] + 63) >> 6;

    const int g = lane >> 2, tig = lane & 3;
    const int a_r = lane & 15;
    const int a_c = (lane & 16) ? 8 : 0;
    const int b_r = (lane & 7) + ((lane & 16) ? 8 : 0);
    const int b_c = (lane & 8) ? 8 : 0;

    const int mj = w & 3;   // j slice [16*mj, +16)
    const int nw = w >> 2;  // i slice [32*nw, +32) (K split; reduced at end)

    // stage resident U tile (single fp16 plane)
    {
        const uint4* sh = (const uint4*)gUh + jc * 512;
        for (int idx = tid; idx < 512; idx += 256) {
            int r = idx >> 3, c = idx & 7;
            *(uint4*)(sm + SM_U + r * 144 + c * 16) = sh[idx];
        }
    }

    float d2[8][4];
#pragma unroll
    for (int nb = 0; nb < 8; nb++)
#pragma unroll
        for (int q = 0; q < 4; q++) d2[nb][q] = 0.f;

    if (nt > 0) {
        stage_load(sb + SM_STG, b, 0, tid);
        CP_COMMIT();
        __syncthreads();  // U visible

        // hoist loop-invariant U A-fragments
        uint32_t uah[4][4];
        {
            const uint32_t ua = sb + SM_U + (16 * mj + a_r) * 144 + a_c * 2;
#pragma unroll
            for (int ks = 0; ks < 4; ks++)
                LDSM4(uah[ks][0], uah[ks][1], uah[ks][2], uah[ks][3], ua + ks * 32);
        }

        for (int t = 0; t < nt; t++) {
            const uint32_t stg = sb + SM_STG + (uint32_t)(t & 1) * STG_SZ;

            CP_WAIT0();
            __syncthreads();  // stage t visible; prior reads of other buffer done

            if (t + 1 < nt) {
                stage_load(sb + SM_STG + (uint32_t)((t + 1) & 1) * STG_SZ, b, t + 1, tid);
                CP_COMMIT();
            }

            // ---- GEMM1: C[16j x 32i], fp16 single-pass ----
            float c1[4][4];
#pragma unroll
            for (int nb = 0; nb < 4; nb++)
#pragma unroll
                for (int q = 0; q < 4; q++) c1[nb][q] = 0.f;

            const uint32_t vbh = stg + (32 * nw + b_r) * 144 + b_c * 2;
#pragma unroll
            for (int ks = 0; ks < 4; ks++) {
                uint32_t bh[8];
#pragma unroll
                for (int p = 0; p < 2; p++)
                    LDSM4(bh[4 * p], bh[4 * p + 1], bh[4 * p + 2], bh[4 * p + 3],
                          vbh + p * 16 * 144 + ks * 32);
#pragma unroll
                for (int nb = 0; nb < 4; nb++) {
                    int bi = (nb >> 1) * 4 + (nb & 1) * 2;
                    MMA_F16(c1[nb], uah[ks][0], uah[ks][1], uah[ks][2], uah[ks][3],
                            bh[bi], bh[bi + 1]);
                }
            }

            // ---- epilogue in registers: sigmoid + mask + fp16 A-frag pack ----
            uint32_t pah[2][4];
#pragma unroll
            for (int nb = 0; nb < 4; nb++) {
                uint32_t i0, i1;
                asm volatile("ld.shared.v2.u32 {%0,%1}, [%2];" : "=r"(i0), "=r"(i1)
                             : "r"(stg + OFF_IDX + (uint32_t)(32 * nw + 8 * nb + 2 * tig) * 4u));
                float tv[4];
#pragma unroll
                for (int q = 0; q < 4; q++) {
                    float x = c1[nb][q] + bias;
                    float s = __fdividef(1.f, 1.f + __expf(-x));
                    int gi = (int)((q & 1) ? i1 : i0);
                    int jg = 64 * jc + 16 * mj + g + ((q & 2) ? 8 : 0);
                    if (gi == jg) s = 0.f;
                    tv[q] = s;
                }
                int ks2 = nb >> 1, ai = 2 * (nb & 1);
                pah[ks2][ai]     = pack2h(__float2half_rn(tv[0]), __float2half_rn(tv[1]));
                pah[ks2][ai + 1] = pack2h(__float2half_rn(tv[2]), __float2half_rn(tv[3]));
            }

            // ---- GEMM2: D2[16j x 64d] += P . (Eh + El), K = warp's 32 i ----
            const uint32_t eb = stg + OFF_EH + b_r * 144u + b_c * 2u + (uint32_t)(64 * nw);
#pragma unroll
            for (int ks2 = 0; ks2 < 2; ks2++) {
#pragma unroll
                for (int p = 0; p < 4; p++) {
                    uint32_t bh[4], bl[4];
                    uint32_t ea = eb + p * 16 * 144 + ks2 * 32;
                    LDSM4(bh[0], bh[1], bh[2], bh[3], ea);
                    LDSM4(bl[0], bl[1], bl[2], bl[3], ea + 9216u);
#pragma unroll
                    for (int blk = 0; blk < 2; blk++) {
                        int nb = 2 * p + blk;
                        MMA_F16(d2[nb], pah[ks2][0], pah[ks2][1], pah[ks2][2], pah[ks2][3],
                                bh[2 * blk], bh[2 * blk + 1]);
                        MMA_F16(d2[nb], pah[ks2][0], pah[ks2][1], pah[ks2][2], pah[ks2][3],
                                bl[2 * blk], bl[2 * blk + 1]);
                    }
                }
            }
        }
    }

    // ---- cross-warp K reduction (nw pairs) + store out (batch b rows) ----
    __syncthreads();
    float* red = (float*)(sm + SM_STG);
    if (nw == 1) {
#pragma unroll
        for (int nb = 0; nb < 8; nb++)
#pragma unroll
            for (int q = 0; q < 4; q++)
                red[(mj * 32 + nb * 4 + q) * 32 + lane] = d2[nb][q];
    }
    __syncthreads();
    if (nw == 0) {
#pragma unroll
        for (int nb = 0; nb < 8; nb++)
#pragma unroll
            for (int q = 0; q < 4; q++)
                d2[nb][q] += red[(mj * 32 + nb * 4 + q) * 32 + lane];
#pragma unroll
        for (int nb = 0; nb < 8; nb++) {
            int d = 8 * nb + 2 * tig;
#pragma unroll
            for (int half = 0; half < 2; half++) {
                int j = 64 * jc + 16 * mj + g + 8 * half;
                size_t off = ((size_t)(b * NN + j)) * 64 + d;
                float2 sv = *(const float2*)(S + off);
                float2 ov;
                ov.x = sv.x + d2[nb][2 * half + 0];
                ov.y = sv.y + d2[nb][2 * half + 1];
                *(float2*)(out + off) = ov;
            }
        }
    }
}

extern "C" void kernel_launch(void* const* d_in, const int* in_sizes, int n_in,
                              void* d_out, int out_size) {
    const float* S    = (const float*)d_in[0];  // task_states   [2,8192,64]
    const float* prof = (const float*)d_in[1];  // proficiency   [2,8192]
    const float* U    = (const float*)d_in[2];  // task_embeddings [8192,64]
    const float* W    = (const float*)d_in[3];  // bilinear_weight [1,64,64]
    const float* bias = (const float*)d_in[4];  // bilinear_bias  [1]
    float* out = (float*)d_out;

    prep_scan<<<2, 1024>>>(prof);
    prep_all<<<384, 256>>>(U, W, S, prof);

    cudaFuncSetAttribute(dyadic_mma, cudaFuncAttributeMaxDynamicSharedMemorySize, SM_TOTAL);
    dyadic_mma<<<256, 256, SM_TOTAL>>>(S, bias, out);
}

// round 17
// speedup vs baseline: 2.7923x; 1.1568x over previous
#include <cuda_runtime.h>
#include <cuda_fp16.h>
#include <cstdint>

#define NN 8192
#define LEAK 0.7f

// ---------------- global scratch (fp16) ----------------
__device__ __align__(16) __half gUh[NN * 64];                    // U[row][k]
__device__ __align__(16) __half gVch[2][(NN + 64) * 64];         // compacted V
__device__ __align__(16) __half gEh[2][128 * 4096];              // [b][c][d][i]
__device__ int g_idx[2][NN + 64];
__device__ int g_cnt[2];

// ---------------- helpers ----------------
__device__ __forceinline__ uint32_t smem_u32(const void* p) {
    uint32_t a;
    asm("{ .reg .u64 t; cvta.to.shared.u64 t, %1; cvt.u32.u64 %0, t; }" : "=r"(a) : "l"(p));
    return a;
}
#define LDSM4(R0, R1, R2, R3, A)                                                 \
    asm volatile("ldmatrix.sync.aligned.m8n8.x4.shared.b16 {%0,%1,%2,%3}, [%4];" \
                 : "=r"(R0), "=r"(R1), "=r"(R2), "=r"(R3) : "r"(A))
#define MMA_F16(c, a0, a1, a2, a3, b0, b1)                                    \
    asm volatile("mma.sync.aligned.m16n8k16.row.col.f32.f16.f16.f32 "         \
                 "{%0,%1,%2,%3},{%4,%5,%6,%7},{%8,%9},{%0,%1,%2,%3};"         \
                 : "+f"((c)[0]), "+f"((c)[1]), "+f"((c)[2]), "+f"((c)[3])     \
                 : "r"(a0), "r"(a1), "r"(a2), "r"(a3), "r"(b0), "r"(b1))
#define CP16(dst, src) \
    asm volatile("cp.async.cg.shared.global [%0], [%1], 16;" :: "r"(dst), "l"(src))
#define CP_COMMIT() asm volatile("cp.async.commit_group;" ::: "memory")
#define CP_WAIT0()  asm volatile("cp.async.wait_group 0;" ::: "memory")

__device__ __forceinline__ uint32_t pack2h(__half a, __half b) {
    return (uint32_t)__half_as_ushort(a) | ((uint32_t)__half_as_ushort(b) << 16);
}

// ---------------- kernel 1: per-batch scan, one block per batch ----------------
__global__ void __launch_bounds__(1024) prep_scan(const float* __restrict__ prof) {
    __shared__ int wsum[32];
    __shared__ int s_cnt;
    const int b = blockIdx.x;
    const int tid = threadIdx.x;
    const int base = tid * 8;

    uint32_t m = 0;
    int local = 0;
#pragma unroll
    for (int q = 0; q < 8; q++) {
        int a = prof[b * NN + base + q] > LEAK;
        m |= ((uint32_t)a) << q;
        local += a;
    }
    int lane = tid & 31, wid = tid >> 5;
    int inc = local;
#pragma unroll
    for (int d = 1; d < 32; d <<= 1) {
        int v = __shfl_up_sync(~0u, inc, d);
        if (lane >= d) inc += v;
    }
    if (lane == 31) wsum[wid] = inc;
    __syncthreads();
    if (wid == 0) {
        int v = wsum[lane];
#pragma unroll
        for (int d = 1; d < 32; d <<= 1) {
            int u = __shfl_up_sync(~0u, v, d);
            if (lane >= d) v += u;
        }
        wsum[lane] = v;
        if (lane == 31) s_cnt = v;
    }
    __syncthreads();
    int excl = inc - local + (wid > 0 ? wsum[wid - 1] : 0);
#pragma unroll
    for (int q = 0; q < 8; q++)
        if ((m >> q) & 1) g_idx[b][excl++] = base + q;

    int cnt = s_cnt;
    if (tid == 0) g_cnt[b] = cnt;
    int pad_end = (cnt + 63) & ~63;
    for (int p = cnt + tid; p < pad_end; p += 1024) g_idx[b][p] = -1;
}

// ---------------- kernel 2: U convert (blocks 0..127) + per-chunk V,E (128..383) ----
__global__ void __launch_bounds__(256) prep_all(const float* __restrict__ U,
                                                const float* __restrict__ W,
                                                const float* __restrict__ S,
                                                const float* __restrict__ prof) {
    int tid = threadIdx.x;
    if (blockIdx.x < 128) {
        int base4 = blockIdx.x * 1024;
        const float4* U4 = (const float4*)U;
#pragma unroll
        for (int idx = tid; idx < 1024; idx += 256) {
            float4 u = U4[base4 + idx];
            uint2 hh;
            hh.x = pack2h(__float2half_rn(u.x), __float2half_rn(u.y));
            hh.y = pack2h(__float2half_rn(u.z), __float2half_rn(u.w));
            ((uint2*)gUh)[base4 + idx] = hh;
        }
        return;
    }

    int lin = blockIdx.x - 128;
    int b = lin >> 7, c = lin & 127;
    int nt = (g_cnt[b] + 63) >> 6;
    if (c >= nt) return;

    __shared__ float Wt[64 * 68];    // [col][e]; reused as es[64][65]
    __shared__ float Ur[64 * 64];
    __shared__ float sg[64];
    __shared__ int sidx[64];

    if (tid < 64) {
        int gi = g_idx[b][c * 64 + tid];
        sidx[tid] = gi;
        float g0 = 0.f;
        if (gi >= 0) {
            g0 = prof[b * NN + gi] - LEAK;
            g0 = g0 > 0.f ? g0 : 0.f;
        }
        sg[tid] = g0;
    }
    for (int i = tid; i < 4096; i += 256) {
        int col = i & 63, e = i >> 6;
        Wt[col * 68 + e] = W[e * 64 + col];
    }
    __syncthreads();

    {
        const float4* U4 = (const float4*)U;
        float4* Ur4 = (float4*)Ur;
        for (int idx = tid; idx < 1024; idx += 256) {
            int r = idx >> 4, f4 = idx & 15;
            int gi = sidx[r];
            Ur4[idx] = (gi >= 0) ? U4[gi * 16 + f4] : make_float4(0.f, 0.f, 0.f, 0.f);
        }
    }
    __syncthreads();

    {
        int col = tid & 63, rq = tid >> 6;
        float acc[16];
#pragma unroll
        for (int q = 0; q < 16; q++) acc[q] = 0.f;
        const float4* wt4 = (const float4*)(Wt + col * 68);
        const float4* Ur4 = (const float4*)Ur;
#pragma unroll
        for (int e4 = 0; e4 < 16; e4++) {
            float4 wv = wt4[e4];
#pragma unroll
            for (int q = 0; q < 16; q++) {
                float4 uv = Ur4[(4 * q + rq) * 16 + e4];
                acc[q] += uv.x * wv.x + uv.y * wv.y + uv.z * wv.z + uv.w * wv.w;
            }
        }
#pragma unroll
        for (int q = 0; q < 16; q++) {
            int r = 4 * q + rq;
            gVch[b][(c * 64 + r) * 64 + col] = __float2half_rn(acc[q]);
        }
    }
    __syncthreads();

    // E: gather gated S into es[i][d], then write fp16 plane [d][i]
    for (int idx = tid; idx < 4096; idx += 256) {
        int r = idx >> 6, d = idx & 63;
        int gi = sidx[r];
        Wt[r * 65 + d] = (gi >= 0) ? S[((size_t)b * NN + gi) * 64 + d] * sg[r] : 0.f;
    }
    __syncthreads();
    {
        int base = c * 4096;
        for (int idx = tid; idx < 4096; idx += 256) {
            int d = idx >> 6, i = idx & 63;
            gEh[b][base + d * 64 + i] = __float2half_rn(Wt[i * 65 + d]);
        }
    }
}

// ---------------- main: per-(j-tile, batch) CTA, 2 CTAs/SM ----------------
// stage: V[0,9216) E[9216,18432) idx[18432,18688)
#define SM_U 0u
#define SM_STG 9216u
#define STG_SZ 18688u
#define OFF_E 9216u
#define OFF_IDX 18432u
#define SM_TOTAL (9216u + 2u * 18688u)   // 46592

__device__ __forceinline__ void stage_load(uint32_t stg, int b, int t, int tid) {
#pragma unroll
    for (int idx = tid; idx < 512; idx += 256) {
        int r = idx >> 3, c = idx & 7;
        uint32_t dst = stg + r * 144u + c * 16u;
        const char* src = (const char*)gVch[b] + ((size_t)t * 4096 + r * 64 + c * 8) * 2;
        CP16(dst, src);
    }
#pragma unroll
    for (int idx = tid; idx < 512; idx += 256) {
        int r = idx >> 3, c = idx & 7;
        uint32_t dst = stg + OFF_E + r * 144u + c * 16u;
        const char* src = (const char*)gEh[b] + ((size_t)t * 4096 + r * 64 + c * 8) * 2;
        CP16(dst, src);
    }
    if (tid < 16)
        CP16(stg + OFF_IDX + tid * 16u, (const char*)(g_idx[b] + t * 64) + tid * 16);
}

__global__ void __launch_bounds__(256, 2) dyadic_mma(const float* __restrict__ S,
                                                     const float* __restrict__ bias_p,
                                                     float* __restrict__ out) {
    extern __shared__ char sm[];
    const uint32_t sb = smem_u32(sm);
    const int tid = threadIdx.x, w = tid >> 5, lane = tid & 31;
    const int jc = blockIdx.x >> 1, b = blockIdx.x & 1;
    const float bias = bias_p[0];
    const int nt = (g_cnt[b] + 63) >> 6;

    const int g = lane >> 2, tig = lane & 3;
    const int a_r = lane & 15;
    const int a_c = (lane & 16) ? 8 : 0;
    const int b_r = (lane & 7) + ((lane & 16) ? 8 : 0);
    const int b_c = (lane & 8) ? 8 : 0;

    const int mj = w & 3;   // j slice [16*mj, +16)
    const int nw = w >> 2;  // i slice [32*nw, +32) (K split; reduced at end)

    // stage resident U tile (single fp16 plane)
    {
        const uint4* sh = (const uint4*)gUh + jc * 512;
        for (int idx = tid; idx < 512; idx += 256) {
            int r = idx >> 3, c = idx & 7;
            *(uint4*)(sm + SM_U + r * 144 + c * 16) = sh[idx];
        }
    }

    float d2[8][4];
#pragma unroll
    for (int nb = 0; nb < 8; nb++)
#pragma unroll
        for (int q = 0; q < 4; q++) d2[nb][q] = 0.f;

    if (nt > 0) {
        stage_load(sb + SM_STG, b, 0, tid);
        CP_COMMIT();
        __syncthreads();  // U visible

        // hoist loop-invariant U A-fragments
        uint32_t uah[4][4];
        {
            const uint32_t ua = sb + SM_U + (16 * mj + a_r) * 144 + a_c * 2;
#pragma unroll
            for (int ks = 0; ks < 4; ks++)
                LDSM4(uah[ks][0], uah[ks][1], uah[ks][2], uah[ks][3], ua + ks * 32);
        }

        for (int t = 0; t < nt; t++) {
            const uint32_t stg = sb + SM_STG + (uint32_t)(t & 1) * STG_SZ;

            CP_WAIT0();
            __syncthreads();  // stage t visible; prior reads of other buffer done

            if (t + 1 < nt) {
                stage_load(sb + SM_STG + (uint32_t)((t + 1) & 1) * STG_SZ, b, t + 1, tid);
                CP_COMMIT();
            }

            // ---- GEMM1: C[16j x 32i], fp16 single-pass ----
            float c1[4][4];
#pragma unroll
            for (int nb = 0; nb < 4; nb++)
#pragma unroll
                for (int q = 0; q < 4; q++) c1[nb][q] = 0.f;

            const uint32_t vbh = stg + (32 * nw + b_r) * 144 + b_c * 2;
#pragma unroll
            for (int ks = 0; ks < 4; ks++) {
                uint32_t bh[8];
#pragma unroll
                for (int p = 0; p < 2; p++)
                    LDSM4(bh[4 * p], bh[4 * p + 1], bh[4 * p + 2], bh[4 * p + 3],
                          vbh + p * 16 * 144 + ks * 32);
#pragma unroll
                for (int nb = 0; nb < 4; nb++) {
                    int bi = (nb >> 1) * 4 + (nb & 1) * 2;
                    MMA_F16(c1[nb], uah[ks][0], uah[ks][1], uah[ks][2], uah[ks][3],
                            bh[bi], bh[bi + 1]);
                }
            }

            // ---- epilogue in registers: sigmoid + mask + fp16 A-frag pack ----
            uint32_t pah[2][4];
#pragma unroll
            for (int nb = 0; nb < 4; nb++) {
                uint32_t i0, i1;
                asm volatile("ld.shared.v2.u32 {%0,%1}, [%2];" : "=r"(i0), "=r"(i1)
                             : "r"(stg + OFF_IDX + (uint32_t)(32 * nw + 8 * nb + 2 * tig) * 4u));
                float tv[4];
#pragma unroll
                for (int q = 0; q < 4; q++) {
                    float x = c1[nb][q] + bias;
                    float s = __fdividef(1.f, 1.f + __expf(-x));
                    int gi = (int)((q & 1) ? i1 : i0);
                    int jg = 64 * jc + 16 * mj + g + ((q & 2) ? 8 : 0);
                    if (gi == jg) s = 0.f;
                    tv[q] = s;
                }
                int ks2 = nb >> 1, ai = 2 * (nb & 1);
                pah[ks2][ai]     = pack2h(__float2half_rn(tv[0]), __float2half_rn(tv[1]));
                pah[ks2][ai + 1] = pack2h(__float2half_rn(tv[2]), __float2half_rn(tv[3]));
            }

            // ---- GEMM2: D2[16j x 64d] += P . E, K = warp's 32 i ----
            const uint32_t eb = stg + OFF_E + b_r * 144u + b_c * 2u + (uint32_t)(64 * nw);
#pragma unroll
            for (int ks2 = 0; ks2 < 2; ks2++) {
#pragma unroll
                for (int p = 0; p < 4; p++) {
                    uint32_t bh[4];
                    uint32_t ea = eb + p * 16 * 144 + ks2 * 32;
                    LDSM4(bh[0], bh[1], bh[2], bh[3], ea);
#pragma unroll
                    for (int blk = 0; blk < 2; blk++) {
                        int nb = 2 * p + blk;
                        MMA_F16(d2[nb], pah[ks2][0], pah[ks2][1], pah[ks2][2], pah[ks2][3],
                                bh[2 * blk], bh[2 * blk + 1]);
                    }
                }
            }
        }
    }

    // ---- cross-warp K reduction (nw pairs) + store out (batch b rows) ----
    __syncthreads();
    float* red = (float*)(sm + SM_STG);
    if (nw == 1) {
#pragma unroll
        for (int nb = 0; nb < 8; nb++)
#pragma unroll
            for (int q = 0; q < 4; q++)
                red[(mj * 32 + nb * 4 + q) * 32 + lane] = d2[nb][q];
    }
    __syncthreads();
    if (nw == 0) {
#pragma unroll
        for (int nb = 0; nb < 8; nb++)
#pragma unroll
            for (int q = 0; q < 4; q++)
                d2[nb][q] += red[(mj * 32 + nb * 4 + q) * 32 + lane];
#pragma unroll
        for (int nb = 0; nb < 8; nb++) {
            int d = 8 * nb + 2 * tig;
#pragma unroll
            for (int half = 0; half < 2; half++) {
                int j = 64 * jc + 16 * mj + g + 8 * half;
                size_t off = ((size_t)(b * NN + j)) * 64 + d;
                float2 sv = *(const float2*)(S + off);
                float2 ov;
                ov.x = sv.x + d2[nb][2 * half + 0];
                ov.y = sv.y + d2[nb][2 * half + 1];
                *(float2*)(out + off) = ov;
            }
        }
    }
}

extern "C" void kernel_launch(void* const* d_in, const int* in_sizes, int n_in,
                              void* d_out, int out_size) {
    const float* S    = (const float*)d_in[0];  // task_states   [2,8192,64]
    const float* prof = (const float*)d_in[1];  // proficiency   [2,8192]
    const float* U    = (const float*)d_in[2];  // task_embeddings [8192,64]
    const float* W    = (const float*)d_in[3];  // bilinear_weight [1,64,64]
    const float* bias = (const float*)d_in[4];  // bilinear_bias  [1]
    float* out = (float*)d_out;

    prep_scan<<<2, 1024>>>(prof);
    prep_all<<<384, 256>>>(U, W, S, prof);

    cudaFuncSetAttribute(dyadic_mma, cudaFuncAttributeMaxDynamicSharedMemorySize, SM_TOTAL);
    dyadic_mma<<<256, 256, SM_TOTAL>>>(S, bias, out);
}